// round 5
// baseline (speedup 1.0000x reference)
#include <cuda_runtime.h>
#include <cuda_bf16.h>
#include <math.h>

// Problem constants
#define NB   16
#define NRW  300
#define CC   150
#define NREL 50
#define RR   3
#define RR2  9
#define NTRI 2700
#define MAXR 100
#define KK   10

// Output float offsets inside d_out
#define O_PRO   0LL
#define O_BOX   2621440LL
#define O_CLS   2662400LL
#define O_REL   4198400LL
#define O_ROI   5509120LL
#define O_VIS   69734400LL

#define FULLMASK 0xffffffffu

// Row widths in vector units
#define D_ROI4 3136
#define D_PRO4 128
#define D_REL4 64
#define D_BOX4 2
#define D_CLS2 150

// Kernel-1 block layout: 16 select blocks, then straight-copy sections (256 thr)
#define SEL_BLKS 16
#define ROI_S_BLKS 58800   // 16*300*3136 /256
#define PRO_S_BLKS 2400    // 16*300*128  /256
#define CLS_S_BLKS 2813    // ceil(16*300*150 /256)
#define REL_S_BLKS 1200    // 16*300*64   /256
#define BOX_S_BLKS 38      // ceil(16*300*2 /256)
#define K1_BLKS (SEL_BLKS + ROI_S_BLKS + PRO_S_BLKS + CLS_S_BLKS + REL_S_BLKS + BOX_S_BLKS)

// Kernel-2 (gather rows 300..319) block layout
#define ROI_G_BLKS 3920    // 16*20*3136 /256
#define PRO_G_BLKS 160
#define CLS_G_BLKS 188     // ceil(16*20*150/256)
#define REL_G_BLKS 80
#define BOX_G_BLKS 3       // ceil(16*20*2/256)
#define K2_BLKS (ROI_G_BLKS + PRO_G_BLKS + CLS_G_BLKS + REL_G_BLKS + BOX_G_BLKS)

__device__ int g_ent[NB * KK];

__device__ __forceinline__ float sigmoidf_(float x) {
    return 1.0f / (1.0f + expf(-x));
}

__device__ __forceinline__ void warp_argmax_bcast(float& v, int& i) {
    #pragma unroll
    for (int o = 16; o; o >>= 1) {
        float ov = __shfl_down_sync(FULLMASK, v, o);
        int   oi = __shfl_down_sync(FULLMASK, i, o);
        if (ov > v || (ov == v && oi < i)) { v = ov; i = oi; }
    }
    v = __shfl_sync(FULLMASK, v, 0);
    i = __shfl_sync(FULLMASK, i, 0);
}

__device__ __forceinline__ void top3_warp(float lv[5], int lane,
                                          float outv[3], int outi[3]) {
    #pragma unroll
    for (int r = 0; r < 3; r++) {
        float bv = -1e30f; int bi = 0x7fffffff;
        #pragma unroll
        for (int k = 0; k < 5; k++) {
            if (lv[k] > bv) { bv = lv[k]; bi = lane + 32 * k; }
        }
        warp_argmax_bcast(bv, bi);
        outv[r] = bv; outi[r] = bi;
        if ((bi & 31) == lane) lv[bi >> 5] = -1e30f;
    }
}

// Straight copy: rows [0,300) of each output, src row r -> out row r.
template <typename VT, int DV>
__device__ __forceinline__ void straight_copy(
    const VT* __restrict__ src, VT* __restrict__ out, int secblk, int tid)
{
    int idx = secblk * 256 + tid;
    if (idx >= NB * NRW * DV) return;
    int c   = idx % DV;
    int row = idx / DV;
    int b = row / NRW, r = row % NRW;
    out[((long long)(b * 320 + r)) * DV + c] = src[idx];
}

// ---------------------------------------------------------------------------
// Kernel 1: blocks [0,16) do full selection for batch b; the rest stream-copy.
// ---------------------------------------------------------------------------
__global__ void __launch_bounds__(256) mega_kernel(
    const float* __restrict__ aux_rel,
    const float* __restrict__ cls_log,   // (16,600,150)
    const float* __restrict__ pred_bb,   // (16,600,4)
    const float* __restrict__ pro,
    const float* __restrict__ roi,
    const float* __restrict__ so_cls,    // (16,300,300)
    const float* __restrict__ pb_so,     // (16,300,8)
    const float* __restrict__ so_pro,
    const float* __restrict__ so_roi,
    const float* __restrict__ rel_lg,    // (16,300,50)
    const float* __restrict__ rel_ft,
    const unsigned char* __restrict__ vis,
    float* __restrict__ out)
{
    const int bid = blockIdx.x;
    const int tid = threadIdx.x;

    if (bid >= SEL_BLKS) {
        // ---------------- streaming straight-copy sections ----------------
        int s = bid - SEL_BLKS;
        if (s < ROI_S_BLKS) {
            straight_copy<float4, D_ROI4>((const float4*)so_roi,
                                          (float4*)(out + O_ROI), s, tid);
            return;
        }
        s -= ROI_S_BLKS;
        if (s < PRO_S_BLKS) {
            straight_copy<float4, D_PRO4>((const float4*)so_pro,
                                          (float4*)(out + O_PRO), s, tid);
            return;
        }
        s -= PRO_S_BLKS;
        if (s < CLS_S_BLKS) {
            straight_copy<float2, D_CLS2>((const float2*)so_cls,
                                          (float2*)(out + O_CLS), s, tid);
            return;
        }
        s -= CLS_S_BLKS;
        if (s < REL_S_BLKS) {
            straight_copy<float4, D_REL4>((const float4*)rel_ft,
                                          (float4*)(out + O_REL), s, tid);
            return;
        }
        s -= REL_S_BLKS;
        straight_copy<float4, D_BOX4>((const float4*)pb_so,
                                      (float4*)(out + O_BOX), s, tid);
        return;
    }

    // ---------------- selection for batch b ----------------
    const int b    = bid;
    const int lane = tid & 31;
    const int wid  = tid >> 5;

    __shared__ float         tri[NTRI];
    __shared__ unsigned char s_cl[NRW][3];
    __shared__ unsigned char o_cl[NRW][3];
    __shared__ unsigned char entcls[NRW];
    __shared__ float         entscore[NRW];
    __shared__ float         entbox[NRW][4];
    __shared__ int           hist[256];
    __shared__ int           tri_idx_sh[MAXR];
    __shared__ short         selcls_sh[2 * MAXR];
    __shared__ float         selbox_sh[2 * MAXR][4];
    __shared__ unsigned char entflag_sh[NRW];
    __shared__ float         redv[8];
    __shared__ int           redi[8];

    // ---- Phase 1: warp-per-row precompute ----
    for (int i = wid; i < NRW; i += 8) {
        const int gw = b * NRW + i;
        const float* row = so_cls + (long long)gw * (2 * CC);

        float lv[5];
        #pragma unroll
        for (int k = 0; k < 5; k++) { int c = lane + 32 * k; lv[k] = (c < CC) ? row[c] : -1e30f; }
        float sv[3]; int si[3];
        top3_warp(lv, lane, sv, si);
        #pragma unroll
        for (int k = 0; k < 5; k++) { int c = lane + 32 * k; lv[k] = (c < CC) ? row[CC + c] : -1e30f; }
        float ov[3]; int oi[3];
        top3_warp(lv, lane, ov, oi);

        const float* rl = rel_lg + (long long)gw * NREL;
        float m = -1e30f;
        #pragma unroll
        for (int k = 0; k < 2; k++) { int c = lane + 32 * k; if (c < NREL) m = fmaxf(m, rl[c]); }
        #pragma unroll
        for (int o = 16; o; o >>= 1) m = fmaxf(m, __shfl_down_sync(FULLMASK, m, o));
        m = __shfl_sync(FULLMASK, m, 0);
        float rmax = sigmoidf_(m);

        float ssig[3], osig[3];
        #pragma unroll
        for (int r = 0; r < 3; r++) { ssig[r] = sigmoidf_(sv[r]); osig[r] = sigmoidf_(ov[r]); }

        if (lane < 9) {
            int X = lane / 3, Y = lane % 3;
            float sV = (X == 0) ? ssig[0] : (X == 1) ? ssig[1] : ssig[2];
            float oV = (Y == 0) ? osig[0] : (Y == 1) ? osig[1] : osig[2];
            tri[i * RR2 + lane] = (rmax * sV) * oV;
        }
        if (lane < 3) {
            s_cl[i][lane] = (unsigned char)si[lane];
            o_cl[i][lane] = (unsigned char)oi[lane];
        }

        // entity = row 2i of cls_logits / pred_bb
        const float* crow = cls_log + (long long)(b * 2 * NRW + 2 * i) * CC;
        float bv = -1e30f; int bi = 0x7fffffff;
        #pragma unroll
        for (int k = 0; k < 5; k++) {
            int c = lane + 32 * k;
            float v = (c < CC) ? crow[c] : -1e30f;
            if (v > bv) { bv = v; bi = c; }
        }
        warp_argmax_bcast(bv, bi);
        if (lane == 0) {
            entcls[i] = (unsigned char)bi;
            float sc = sigmoidf_(bv);
            if (vis[b * NRW + i]) sc -= 2.0f;
            entscore[i] = sc;
            entflag_sh[i] = 0;
        }
        const float* bb = pred_bb + (long long)(b * 2 * NRW + 2 * i) * 4;
        if (lane < 4) entbox[i][lane] = bb[lane];
    }
    __syncthreads();

    // ---- Phase 2: radix select 100th-largest (keys are positive floats) ----
    unsigned prefval = 0, prefmask = 0;
    int rem = MAXR;
    #pragma unroll
    for (int shift = 24; shift >= 0; shift -= 8) {
        hist[tid] = 0;
        __syncthreads();
        for (int t = tid; t < NTRI; t += 256) {
            unsigned k = __float_as_uint(tri[t]);
            if ((k & prefmask) == prefval)
                atomicAdd(&hist[(k >> shift) & 0xff], 1);
        }
        __syncthreads();
        int c = 0, d = 255;
        for (; d >= 0; --d) {
            int h = hist[d];
            if (c + h >= rem) break;
            c += h;
        }
        rem -= c;
        prefval  |= ((unsigned)d) << shift;
        prefmask |= 0xffu << shift;
        __syncthreads();
    }
    const unsigned thr = prefval;
    const int E = rem;

    // ---- Phase 3: flag + compact (ascending) in one pass, warp 0 ----
    if (tid < 32) {
        int total = 0, eqbase = 0;
        for (int s0 = 0; s0 < NTRI; s0 += 32) {
            int t = s0 + lane;
            bool inb = t < NTRI;
            unsigned key = inb ? __float_as_uint(tri[t]) : 0u;
            bool eq = inb && (key == thr);
            unsigned eqbal = __ballot_sync(FULLMASK, eq);
            int eqrank = eqbase + __popc(eqbal & ((1u << lane) - 1));
            bool sel = (inb && key > thr) || (eq && eqrank < E);
            unsigned selbal = __ballot_sync(FULLMASK, sel);
            int pos = total + __popc(selbal & ((1u << lane) - 1));
            if (sel) tri_idx_sh[pos] = t;
            total += __popc(selbal);
            eqbase += __popc(eqbal);
        }
    }
    __syncthreads();

    // ---- Phase 4: gather selected classes & boxes ----
    if (tid < MAXR) {
        int t = tri_idx_sh[tid];
        int i = t / RR2, p = t % RR2;
        int X = p / RR, Y = p % RR;
        selcls_sh[2 * tid]     = s_cl[i][X];
        selcls_sh[2 * tid + 1] = o_cl[i][Y];
        const float* bx = pb_so + (long long)(b * NRW + i) * 8;
        selbox_sh[2 * tid][0]     = bx[0]; selbox_sh[2 * tid][1]     = bx[1];
        selbox_sh[2 * tid][2]     = bx[2]; selbox_sh[2 * tid][3]     = bx[3];
        selbox_sh[2 * tid + 1][0] = bx[4]; selbox_sh[2 * tid + 1][1] = bx[5];
        selbox_sh[2 * tid + 1][2] = bx[6]; selbox_sh[2 * tid + 1][3] = bx[7];
    }
    __syncthreads();

    // ---- Phase 5: IoU dedup (warp per entity) ----
    for (int i = wid; i < NRW; i += 8) {
        int cls  = entcls[i];
        float x1 = entbox[i][0], y1 = entbox[i][1];
        float x2 = entbox[i][2], y2 = entbox[i][3];
        float a1 = (y2 - y1 + 1.0f) * (x2 - x1 + 1.0f);
        bool hit = false;
        for (int j = lane; j < 2 * MAXR; j += 32) {
            if (selcls_sh[j] != cls) continue;
            float bx1 = selbox_sh[j][0], by1 = selbox_sh[j][1];
            float bx2 = selbox_sh[j][2], by2 = selbox_sh[j][3];
            float a2  = (by2 - by1 + 1.0f) * (bx2 - bx1 + 1.0f);
            float ltx = fmaxf(x1, bx1), lty = fmaxf(y1, by1);
            float rbx = fminf(x2, bx2), rby = fminf(y2, by2);
            float w = fmaxf(rbx - ltx, 0.0f), h = fmaxf(rby - lty, 0.0f);
            float inter = w * h;
            if (inter / (a1 + a2 - inter) >= 0.5f) hit = true;
        }
        if (__any_sync(FULLMASK, hit) && lane == 0)
            entscore[i] -= 2.0f;
    }
    __syncthreads();

    // ---- Phase 6: top-10 entities ----
    for (int it = 0; it < KK; it++) {
        float bv = -1e30f; int bi = 0x7fffffff;
        for (int i = tid; i < NRW; i += 256) {
            if (entflag_sh[i]) continue;
            float v = entscore[i];
            if (v > bv || (v == bv && i < bi)) { bv = v; bi = i; }
        }
        #pragma unroll
        for (int o = 16; o; o >>= 1) {
            float ov = __shfl_down_sync(FULLMASK, bv, o);
            int   oi = __shfl_down_sync(FULLMASK, bi, o);
            if (ov > bv || (ov == bv && oi < bi)) { bv = ov; bi = oi; }
        }
        if (lane == 0) { redv[wid] = bv; redi[wid] = bi; }
        __syncthreads();
        if (tid == 0) {
            float fv = redv[0]; int fi = redi[0];
            for (int w = 1; w < 8; w++)
                if (redv[w] > fv || (redv[w] == fv && redi[w] < fi)) { fv = redv[w]; fi = redi[w]; }
            entflag_sh[fi] = 1;
        }
        __syncthreads();
    }

    // ---- Phase 7: emit g_ent (ascending) + vis_out ----
    if (tid < 32) {
        int total = 0;
        for (int s0 = 0; s0 < NRW; s0 += 32) {
            int t = s0 + lane;
            bool f = (t < NRW) && entflag_sh[t];
            unsigned bal = __ballot_sync(FULLMASK, f);
            int pos = total + __popc(bal & ((1u << lane) - 1));
            if (f) g_ent[b * KK + pos] = t;
            total += __popc(bal);
        }
    }
    __syncthreads();
    for (int i = tid; i < NRW; i += 256)
        out[O_VIS + b * NRW + i] = (vis[b * NRW + i] || entflag_sh[i]) ? 1.0f : 0.0f;
}

// ---------------------------------------------------------------------------
// Kernel 2: gathered rows [300,320) for all five outputs (reads g_ent).
// ---------------------------------------------------------------------------
template <typename VT, int DV, int GSV, int OFF2>
__device__ __forceinline__ void gather_copy(
    const VT* __restrict__ gsrc, VT* __restrict__ out, int secblk, int tid)
{
    int idx = secblk * 256 + tid;
    if (idx >= NB * 2 * KK * DV) return;
    int c    = idx % DV;
    int rowg = idx / DV;
    int b  = rowg / (2 * KK);
    int rk = rowg % (2 * KK);
    int k  = (rk < KK) ? rk : rk - KK;
    int off = (rk < KK) ? 0 : OFF2;
    int e = g_ent[b * KK + k];
    int col = c + off; if (col >= GSV) col -= GSV;
    VT v = gsrc[((long long)(b * NRW + e)) * GSV + col];
    out[((long long)(b * 320 + NRW + rk)) * DV + c] = v;
}

__global__ void __launch_bounds__(256) gather_kernel(
    const float* __restrict__ aux_rel,
    const float* __restrict__ cls_log,
    const float* __restrict__ pred_bb,
    const float* __restrict__ pro,
    const float* __restrict__ roi,
    const float* __restrict__ so_cls,
    float* __restrict__ out)
{
    int s = blockIdx.x;
    int tid = threadIdx.x;
    if (s < ROI_G_BLKS) {
        gather_copy<float4, D_ROI4, D_ROI4, 1568>((const float4*)roi,
                                                  (float4*)(out + O_ROI), s, tid);
        return;
    }
    s -= ROI_G_BLKS;
    if (s < PRO_G_BLKS) {
        gather_copy<float4, D_PRO4, D_PRO4, 64>((const float4*)pro,
                                                (float4*)(out + O_PRO), s, tid);
        return;
    }
    s -= PRO_G_BLKS;
    if (s < CLS_G_BLKS) {
        gather_copy<float2, D_CLS2, D_CLS2, 75>((const float2*)cls_log,
                                                (float2*)(out + O_CLS), s, tid);
        return;
    }
    s -= CLS_G_BLKS;
    if (s < REL_G_BLKS) {
        // rel: out rows 64 f4, src rows 128 f4, second half at +64
        gather_copy<float4, D_REL4, 128, 64>((const float4*)aux_rel,
                                             (float4*)(out + O_REL), s, tid);
        return;
    }
    s -= REL_G_BLKS;
    gather_copy<float4, D_BOX4, D_BOX4, 1>((const float4*)pred_bb,
                                           (float4*)(out + O_BOX), s, tid);
}

extern "C" void kernel_launch(void* const* d_in, const int* in_sizes, int n_in,
                              void* d_out, int out_size)
{
    const float* aux_rel = (const float*)d_in[0];
    const float* cls_log = (const float*)d_in[1];
    const float* pred_bb = (const float*)d_in[2];
    const float* pro     = (const float*)d_in[3];
    const float* roi     = (const float*)d_in[4];
    const float* so_cls  = (const float*)d_in[5];
    const float* pb_so   = (const float*)d_in[6];
    const float* so_pro  = (const float*)d_in[7];
    const float* so_roi  = (const float*)d_in[8];
    const float* rel_lg  = (const float*)d_in[9];
    const float* rel_ft  = (const float*)d_in[10];
    const unsigned char* vis = (const unsigned char*)d_in[11];

    float* out = (float*)d_out;

    mega_kernel<<<K1_BLKS, 256>>>(aux_rel, cls_log, pred_bb, pro, roi, so_cls,
                                  pb_so, so_pro, so_roi, rel_lg, rel_ft, vis, out);

    gather_kernel<<<K2_BLKS, 256>>>(aux_rel, cls_log, pred_bb, pro, roi, so_cls, out);
}

// round 10
// speedup vs baseline: 1.3101x; 1.3101x over previous
#include <cuda_runtime.h>
#include <cuda_bf16.h>
#include <math.h>

// Problem constants
#define NB   16
#define NRW  300
#define CC   150
#define NREL 50
#define RR   3
#define RR2  9
#define NTRI 2700
#define MAXR 100
#define KK   10

// Output float offsets inside d_out
#define O_PRO   0LL
#define O_BOX   2621440LL
#define O_CLS   2662400LL
#define O_REL   4198400LL
#define O_ROI   5509120LL
#define O_VIS   69734400LL

#define FULLMASK 0xffffffffu

// Row widths in vector units
#define D_ROI4 3136
#define D_PRO4 128
#define D_REL4 64
#define D_BOX4 2
#define D_CLS2 150

// Copy-kernel block layout (256 threads per block)
#define ROI_S_BLKS 58800   // 16*300*3136 /256
#define PRO_S_BLKS 2400    // 16*300*128  /256
#define CLS_S_BLKS 2813    // ceil(16*300*150 /256)
#define REL_S_BLKS 1200    // 16*300*64   /256
#define BOX_S_BLKS 38      // ceil(16*300*2 /256)
#define ROI_G_BLKS 3920    // 16*20*3136 /256
#define PRO_G_BLKS 160
#define CLS_G_BLKS 188     // ceil(16*20*150/256)
#define REL_G_BLKS 80
#define BOX_G_BLKS 3
#define K2_BLKS (ROI_S_BLKS + PRO_S_BLKS + CLS_S_BLKS + REL_S_BLKS + BOX_S_BLKS + \
                 ROI_G_BLKS + PRO_G_BLKS + CLS_G_BLKS + REL_G_BLKS + BOX_G_BLKS)

__device__ int g_ent[NB * KK];

__device__ __forceinline__ float sigmoidf_(float x) {
    return 1.0f / (1.0f + expf(-x));
}

__device__ __forceinline__ void warp_argmax_bcast(float& v, int& i) {
    #pragma unroll
    for (int o = 16; o; o >>= 1) {
        float ov = __shfl_down_sync(FULLMASK, v, o);
        int   oi = __shfl_down_sync(FULLMASK, i, o);
        if (ov > v || (ov == v && oi < i)) { v = ov; i = oi; }
    }
    v = __shfl_sync(FULLMASK, v, 0);
    i = __shfl_sync(FULLMASK, i, 0);
}

__device__ __forceinline__ void top3_warp(float lv[5], int lane,
                                          float outv[3], int outi[3]) {
    #pragma unroll
    for (int r = 0; r < 3; r++) {
        float bv = -1e30f; int bi = 0x7fffffff;
        #pragma unroll
        for (int k = 0; k < 5; k++) {
            if (lv[k] > bv) { bv = lv[k]; bi = lane + 32 * k; }
        }
        warp_argmax_bcast(bv, bi);
        outv[r] = bv; outi[r] = bi;
        if ((bi & 31) == lane) lv[bi >> 5] = -1e30f;
    }
}

// ---------------------------------------------------------------------------
// K1: one block per batch, 1024 threads. Full selection pipeline, quiet machine.
// ---------------------------------------------------------------------------
__global__ void __launch_bounds__(1024) select_kernel(
    const float* __restrict__ so_cls,    // (16,300,300)
    const float* __restrict__ rel_lg,    // (16,300,50)
    const float* __restrict__ cls_log,   // (16,600,150)
    const float* __restrict__ pred_bb,   // (16,600,4)
    const float* __restrict__ pb_so,     // (16,300,8)
    const unsigned char* __restrict__ vis,
    float* __restrict__ out)
{
    const int b    = blockIdx.x;
    const int tid  = threadIdx.x;
    const int lane = tid & 31;
    const int wid  = tid >> 5;

    __shared__ float         tri[NTRI];
    __shared__ unsigned char s_cl[NRW][3];
    __shared__ unsigned char o_cl[NRW][3];
    __shared__ unsigned char entcls[NRW];
    __shared__ float         entscore[NRW];
    __shared__ float         entbox[NRW][4];
    __shared__ int           hist[256];
    __shared__ int           tri_idx_sh[MAXR];
    __shared__ short         selcls_sh[2 * MAXR];
    __shared__ float         selbox_sh[2 * MAXR][4];
    __shared__ unsigned char entflag_sh[NRW];
    __shared__ float         redv[32];
    __shared__ int           redi[32];

    // ---- Phase 1: warp-per-row precompute (32 warps, ~10 rows each) ----
    for (int i = wid; i < NRW; i += 32) {
        const int gw = b * NRW + i;
        const float* row = so_cls + (long long)gw * (2 * CC);

        float lv[5];
        #pragma unroll
        for (int k = 0; k < 5; k++) { int c = lane + 32 * k; lv[k] = (c < CC) ? row[c] : -1e30f; }
        float sv[3]; int si[3];
        top3_warp(lv, lane, sv, si);
        #pragma unroll
        for (int k = 0; k < 5; k++) { int c = lane + 32 * k; lv[k] = (c < CC) ? row[CC + c] : -1e30f; }
        float ov[3]; int oi[3];
        top3_warp(lv, lane, ov, oi);

        const float* rl = rel_lg + (long long)gw * NREL;
        float m = -1e30f;
        #pragma unroll
        for (int k = 0; k < 2; k++) { int c = lane + 32 * k; if (c < NREL) m = fmaxf(m, rl[c]); }
        #pragma unroll
        for (int o = 16; o; o >>= 1) m = fmaxf(m, __shfl_down_sync(FULLMASK, m, o));
        m = __shfl_sync(FULLMASK, m, 0);
        float rmax = sigmoidf_(m);

        float ssig[3], osig[3];
        #pragma unroll
        for (int r = 0; r < 3; r++) { ssig[r] = sigmoidf_(sv[r]); osig[r] = sigmoidf_(ov[r]); }

        if (lane < 9) {
            int X = lane / 3, Y = lane % 3;
            float sV = (X == 0) ? ssig[0] : (X == 1) ? ssig[1] : ssig[2];
            float oV = (Y == 0) ? osig[0] : (Y == 1) ? osig[1] : osig[2];
            tri[i * RR2 + lane] = (rmax * sV) * oV;
        }
        if (lane < 3) {
            s_cl[i][lane] = (unsigned char)si[lane];
            o_cl[i][lane] = (unsigned char)oi[lane];
        }

        // entity = row 2i of cls_logits / pred_bb
        const float* crow = cls_log + (long long)(b * 2 * NRW + 2 * i) * CC;
        float bv = -1e30f; int bi = 0x7fffffff;
        #pragma unroll
        for (int k = 0; k < 5; k++) {
            int c = lane + 32 * k;
            float v = (c < CC) ? crow[c] : -1e30f;
            if (v > bv) { bv = v; bi = c; }
        }
        warp_argmax_bcast(bv, bi);
        if (lane == 0) {
            entcls[i] = (unsigned char)bi;
            float sc = sigmoidf_(bv);
            if (vis[b * NRW + i]) sc -= 2.0f;
            entscore[i] = sc;
            entflag_sh[i] = 0;
        }
        const float* bb = pred_bb + (long long)(b * 2 * NRW + 2 * i) * 4;
        if (lane < 4) entbox[i][lane] = bb[lane];
    }
    __syncthreads();

    // ---- Phase 2: 4-pass radix select for the 100th-largest key ----
    unsigned prefval = 0, prefmask = 0;
    int rem = MAXR;
    #pragma unroll
    for (int shift = 24; shift >= 0; shift -= 8) {
        if (tid < 256) hist[tid] = 0;
        __syncthreads();
        for (int t = tid; t < NTRI; t += 1024) {
            unsigned k = __float_as_uint(tri[t]);
            if ((k & prefmask) == prefval)
                atomicAdd(&hist[(k >> shift) & 0xff], 1);
        }
        __syncthreads();
        int c = 0, d = 255;
        for (; d >= 0; --d) {
            int h = hist[d];
            if (c + h >= rem) break;
            c += h;
        }
        rem -= c;
        prefval  |= ((unsigned)d) << shift;
        prefmask |= 0xffu << shift;
        __syncthreads();
    }
    const unsigned thr = prefval;
    const int E = rem;

    // ---- Phase 3: flag + compact (ascending) in one pass, warp 0 ----
    if (tid < 32) {
        int total = 0, eqbase = 0;
        for (int s0 = 0; s0 < NTRI; s0 += 32) {
            int t = s0 + lane;
            bool inb = t < NTRI;
            unsigned key = inb ? __float_as_uint(tri[t]) : 0u;
            bool eq = inb && (key == thr);
            unsigned eqbal = __ballot_sync(FULLMASK, eq);
            int eqrank = eqbase + __popc(eqbal & ((1u << lane) - 1));
            bool sel = (inb && key > thr) || (eq && eqrank < E);
            unsigned selbal = __ballot_sync(FULLMASK, sel);
            int pos = total + __popc(selbal & ((1u << lane) - 1));
            if (sel) tri_idx_sh[pos] = t;
            total += __popc(selbal);
            eqbase += __popc(eqbal);
        }
    }
    __syncthreads();

    // ---- Phase 4: gather selected classes & boxes ----
    if (tid < MAXR) {
        int t = tri_idx_sh[tid];
        int i = t / RR2, p = t % RR2;
        int X = p / RR, Y = p % RR;
        selcls_sh[2 * tid]     = s_cl[i][X];
        selcls_sh[2 * tid + 1] = o_cl[i][Y];
        const float* bx = pb_so + (long long)(b * NRW + i) * 8;
        selbox_sh[2 * tid][0]     = bx[0]; selbox_sh[2 * tid][1]     = bx[1];
        selbox_sh[2 * tid][2]     = bx[2]; selbox_sh[2 * tid][3]     = bx[3];
        selbox_sh[2 * tid + 1][0] = bx[4]; selbox_sh[2 * tid + 1][1] = bx[5];
        selbox_sh[2 * tid + 1][2] = bx[6]; selbox_sh[2 * tid + 1][3] = bx[7];
    }
    __syncthreads();

    // ---- Phase 5: IoU dedup (warp per entity, 32 warps) ----
    for (int i = wid; i < NRW; i += 32) {
        int cls  = entcls[i];
        float x1 = entbox[i][0], y1 = entbox[i][1];
        float x2 = entbox[i][2], y2 = entbox[i][3];
        float a1 = (y2 - y1 + 1.0f) * (x2 - x1 + 1.0f);
        bool hit = false;
        for (int j = lane; j < 2 * MAXR; j += 32) {
            if (selcls_sh[j] != cls) continue;
            float bx1 = selbox_sh[j][0], by1 = selbox_sh[j][1];
            float bx2 = selbox_sh[j][2], by2 = selbox_sh[j][3];
            float a2  = (by2 - by1 + 1.0f) * (bx2 - bx1 + 1.0f);
            float ltx = fmaxf(x1, bx1), lty = fmaxf(y1, by1);
            float rbx = fminf(x2, bx2), rby = fminf(y2, by2);
            float w = fmaxf(rbx - ltx, 0.0f), h = fmaxf(rby - lty, 0.0f);
            float inter = w * h;
            if (inter / (a1 + a2 - inter) >= 0.5f) hit = true;
        }
        if (__any_sync(FULLMASK, hit) && lane == 0)
            entscore[i] -= 2.0f;
    }
    __syncthreads();

    // ---- Phase 6: top-10 entities (one value per thread) ----
    for (int it = 0; it < KK; it++) {
        float v = (tid < NRW && !entflag_sh[tid]) ? entscore[tid] : -1e30f;
        int   i = (tid < NRW) ? tid : 0x7fffffff;
        #pragma unroll
        for (int o = 16; o; o >>= 1) {
            float ovv = __shfl_down_sync(FULLMASK, v, o);
            int   oii = __shfl_down_sync(FULLMASK, i, o);
            if (ovv > v || (ovv == v && oii < i)) { v = ovv; i = oii; }
        }
        if (lane == 0) { redv[wid] = v; redi[wid] = i; }
        __syncthreads();
        if (tid == 0) {
            float fv = redv[0]; int fi = redi[0];
            for (int w = 1; w < 32; w++)
                if (redv[w] > fv || (redv[w] == fv && redi[w] < fi)) { fv = redv[w]; fi = redi[w]; }
            entflag_sh[fi] = 1;
        }
        __syncthreads();
    }

    // ---- Phase 7: emit g_ent (ascending) + vis_out ----
    if (tid < 32) {
        int total = 0;
        for (int s0 = 0; s0 < NRW; s0 += 32) {
            int t = s0 + lane;
            bool f = (t < NRW) && entflag_sh[t];
            unsigned bal = __ballot_sync(FULLMASK, f);
            int pos = total + __popc(bal & ((1u << lane) - 1));
            if (f) g_ent[b * KK + pos] = t;
            total += __popc(bal);
        }
    }
    __syncthreads();
    if (tid < NRW)
        out[O_VIS + b * NRW + tid] = (vis[b * NRW + tid] || entflag_sh[tid]) ? 1.0f : 0.0f;
}

// ---------------------------------------------------------------------------
// K2: one launch for ALL copies (straight + gather; g_ent ready after K1).
// ---------------------------------------------------------------------------
template <typename VT, int DV>
__device__ __forceinline__ void straight_copy(
    const VT* __restrict__ src, VT* __restrict__ out, int secblk, int tid)
{
    int idx = secblk * 256 + tid;
    if (idx >= NB * NRW * DV) return;
    int c   = idx % DV;
    int row = idx / DV;
    int b = row / NRW, r = row % NRW;
    out[((long long)(b * 320 + r)) * DV + c] = src[idx];
}

template <typename VT, int DV, int GSV, int OFF2>
__device__ __forceinline__ void gather_copy(
    const VT* __restrict__ gsrc, VT* __restrict__ out, int secblk, int tid)
{
    int idx = secblk * 256 + tid;
    if (idx >= NB * 2 * KK * DV) return;
    int c    = idx % DV;
    int rowg = idx / DV;
    int b  = rowg / (2 * KK);
    int rk = rowg % (2 * KK);
    int k  = (rk < KK) ? rk : rk - KK;
    int off = (rk < KK) ? 0 : OFF2;
    int e = g_ent[b * KK + k];
    int col = c + off; if (col >= GSV) col -= GSV;
    VT v = gsrc[((long long)(b * NRW + e)) * GSV + col];
    out[((long long)(b * 320 + NRW + rk)) * DV + c] = v;
}

__global__ void __launch_bounds__(256) copy_kernel(
    const float* __restrict__ aux_rel,
    const float* __restrict__ cls_log,
    const float* __restrict__ pred_bb,
    const float* __restrict__ pro,
    const float* __restrict__ roi,
    const float* __restrict__ so_cls,
    const float* __restrict__ pb_so,
    const float* __restrict__ so_pro,
    const float* __restrict__ so_roi,
    const float* __restrict__ rel_ft,
    float* __restrict__ out)
{
    int s = blockIdx.x;
    int tid = threadIdx.x;

    if (s < ROI_S_BLKS) {
        straight_copy<float4, D_ROI4>((const float4*)so_roi, (float4*)(out + O_ROI), s, tid);
        return;
    }
    s -= ROI_S_BLKS;
    if (s < ROI_G_BLKS) {
        gather_copy<float4, D_ROI4, D_ROI4, 1568>((const float4*)roi, (float4*)(out + O_ROI), s, tid);
        return;
    }
    s -= ROI_G_BLKS;
    if (s < PRO_S_BLKS) {
        straight_copy<float4, D_PRO4>((const float4*)so_pro, (float4*)(out + O_PRO), s, tid);
        return;
    }
    s -= PRO_S_BLKS;
    if (s < PRO_G_BLKS) {
        gather_copy<float4, D_PRO4, D_PRO4, 64>((const float4*)pro, (float4*)(out + O_PRO), s, tid);
        return;
    }
    s -= PRO_G_BLKS;
    if (s < CLS_S_BLKS) {
        straight_copy<float2, D_CLS2>((const float2*)so_cls, (float2*)(out + O_CLS), s, tid);
        return;
    }
    s -= CLS_S_BLKS;
    if (s < CLS_G_BLKS) {
        gather_copy<float2, D_CLS2, D_CLS2, 75>((const float2*)cls_log, (float2*)(out + O_CLS), s, tid);
        return;
    }
    s -= CLS_G_BLKS;
    if (s < REL_S_BLKS) {
        straight_copy<float4, D_REL4>((const float4*)rel_ft, (float4*)(out + O_REL), s, tid);
        return;
    }
    s -= REL_S_BLKS;
    if (s < REL_G_BLKS) {
        gather_copy<float4, D_REL4, 128, 64>((const float4*)aux_rel, (float4*)(out + O_REL), s, tid);
        return;
    }
    s -= REL_G_BLKS;
    if (s < BOX_S_BLKS) {
        straight_copy<float4, D_BOX4>((const float4*)pb_so, (float4*)(out + O_BOX), s, tid);
        return;
    }
    s -= BOX_S_BLKS;
    gather_copy<float4, D_BOX4, D_BOX4, 1>((const float4*)pred_bb, (float4*)(out + O_BOX), s, tid);
}

extern "C" void kernel_launch(void* const* d_in, const int* in_sizes, int n_in,
                              void* d_out, int out_size)
{
    const float* aux_rel = (const float*)d_in[0];
    const float* cls_log = (const float*)d_in[1];
    const float* pred_bb = (const float*)d_in[2];
    const float* pro     = (const float*)d_in[3];
    const float* roi     = (const float*)d_in[4];
    const float* so_cls  = (const float*)d_in[5];
    const float* pb_so   = (const float*)d_in[6];
    const float* so_pro  = (const float*)d_in[7];
    const float* so_roi  = (const float*)d_in[8];
    const float* rel_lg  = (const float*)d_in[9];
    const float* rel_ft  = (const float*)d_in[10];
    const unsigned char* vis = (const unsigned char*)d_in[11];

    float* out = (float*)d_out;

    select_kernel<<<NB, 1024>>>(so_cls, rel_lg, cls_log, pred_bb, pb_so, vis, out);

    copy_kernel<<<K2_BLKS, 256>>>(aux_rel, cls_log, pred_bb, pro, roi, so_cls,
                                  pb_so, so_pro, so_roi, rel_ft, out);
}